// round 1
// baseline (speedup 1.0000x reference)
#include <cuda_runtime.h>

// AntisymmetricLayer: out[b,n,k] = (z·W_lin[k]) + sum_r (z·P[k,:,r]) * (s·Q[k,:,r])
//   z = x1 - x2, s = x1 + x2
// Shapes: x1,x2: (131072, 128) f32 flat; W_lin: (64,128); P,Q: (64,128,16); out: (131072, 64)
//
// Strategy (round 1, fp32 CUDA cores, FMA-pipe bound):
//   - CTA tile: 64 tokens. Stage z,s token-major in smem.
//   - lin = z @ W^T computed once into smem (W staged d-major to keep reads vectorized).
//   - 8 k-groups of 8 k each: stage P,Q slabs [d=128][c=128] (c = k_local*16 + r) in smem,
//     register tile 4 rows x 8 cols per thread for BOTH zP and sQ accumulators.
//   - Epilogue: per-thread partial dot over 8 r, shfl_xor(1) to complete 16-r reduction,
//     even-tx lanes add lin and store.

#define D128 128
#define MTILE 64
#define KTOT 64
#define KG 8
#define NKG (KTOT / KG)
#define THREADS 256

// dynamic smem layout in floats
#define ZSH_OFF 0
#define SSH_OFF (MTILE * D128)                  // 8192
#define LIN_OFF (SSH_OFF + MTILE * D128)        // 16384
#define PSH_OFF (LIN_OFF + MTILE * KTOT)        // 20480
#define QSH_OFF (PSH_OFF + D128 * 128)          // 36864
#define SMEM_FLOATS (QSH_OFF + D128 * 128)      // 53248 floats = 212992 bytes

__global__ __launch_bounds__(THREADS, 1)
void antisym_kernel(const float* __restrict__ x1,
                    const float* __restrict__ x2,
                    const float* __restrict__ W,
                    const float* __restrict__ P,
                    const float* __restrict__ Q,
                    float* __restrict__ out)
{
    extern __shared__ float sm[];
    float* zsh   = sm + ZSH_OFF;   // [m][d] 64x128
    float* ssh   = sm + SSH_OFF;   // [m][d] 64x128
    float* linsh = sm + LIN_OFF;   // [m][k] 64x64
    float* Psh   = sm + PSH_OFF;   // [d][c] 128x128 ; phase-1 alias: Wsh[d][k] 128x64
    float* Qsh   = sm + QSH_OFF;   // [d][c] 128x128

    const int tid = threadIdx.x;
    const int tx  = tid & 15;      // 0..15
    const int ty  = tid >> 4;      // 0..15
    const int mbase = blockIdx.x * MTILE;

    // ---------- Phase 0: stage z = x1-x2, s = x1+x2 (token-major, coalesced) ----------
    {
        const float4* x1v = reinterpret_cast<const float4*>(x1) + (size_t)mbase * 32;
        const float4* x2v = reinterpret_cast<const float4*>(x2) + (size_t)mbase * 32;
        #pragma unroll
        for (int f = tid; f < MTILE * 32; f += THREADS) {
            int m = f >> 5, d4 = f & 31;
            float4 a = x1v[m * 32 + d4];
            float4 b = x2v[m * 32 + d4];
            float4 z = make_float4(a.x - b.x, a.y - b.y, a.z - b.z, a.w - b.w);
            float4 s = make_float4(a.x + b.x, a.y + b.y, a.z + b.z, a.w + b.w);
            *reinterpret_cast<float4*>(&zsh[m * D128 + d4 * 4]) = z;
            *reinterpret_cast<float4*>(&ssh[m * D128 + d4 * 4]) = s;
        }
    }

    // ---------- Phase 1a: stage W transposed into Psh alias: Wsh[d][k] ----------
    {
        const float4* Wv = reinterpret_cast<const float4*>(W);  // [k][d4] 64x32
        #pragma unroll
        for (int f = tid; f < KTOT * 32; f += THREADS) {
            int k = f & 63, d4 = f >> 6;   // lanes vary k -> conflict-free STS
            float4 w = Wv[k * 32 + d4];
            Psh[(d4 * 4 + 0) * KTOT + k] = w.x;
            Psh[(d4 * 4 + 1) * KTOT + k] = w.y;
            Psh[(d4 * 4 + 2) * KTOT + k] = w.z;
            Psh[(d4 * 4 + 3) * KTOT + k] = w.w;
        }
    }
    __syncthreads();

    // ---------- Phase 1b: lin[m][k] = z @ W^T (thread: 4 rows x 4 k) ----------
    {
        float lacc[4][4] = {};
        #pragma unroll 4
        for (int d = 0; d < D128; d++) {
            float za[4];
            #pragma unroll
            for (int i = 0; i < 4; i++) za[i] = zsh[(ty * 4 + i) * D128 + d];
            float4 w = *reinterpret_cast<const float4*>(&Psh[d * KTOT + tx * 4]);
            #pragma unroll
            for (int i = 0; i < 4; i++) {
                lacc[i][0] += za[i] * w.x;
                lacc[i][1] += za[i] * w.y;
                lacc[i][2] += za[i] * w.z;
                lacc[i][3] += za[i] * w.w;
            }
        }
        #pragma unroll
        for (int i = 0; i < 4; i++) {
            float4 v = make_float4(lacc[i][0], lacc[i][1], lacc[i][2], lacc[i][3]);
            *reinterpret_cast<float4*>(&linsh[(ty * 4 + i) * KTOT + tx * 4]) = v;
        }
    }
    __syncthreads();

    // ---------- Phase 2: k-groups ----------
    for (int kg = 0; kg < NKG; kg++) {
        const int k0 = kg * KG;

        // stage P,Q slab: Psh[d][c], c = k_local*16 + r (global reads are 64B rows, L2-hot)
        #pragma unroll
        for (int f = tid; f < D128 * 32; f += THREADS) {
            int d = f >> 5, c4 = f & 31;
            int c = c4 * 4;
            int kl = c >> 4, r = c & 15;
            size_t g = (((size_t)(k0 + kl) * D128 + d) << 4) + r;  // *16
            *reinterpret_cast<float4*>(&Psh[d * 128 + c]) =
                *reinterpret_cast<const float4*>(&P[g]);
            *reinterpret_cast<float4*>(&Qsh[d * 128 + c]) =
                *reinterpret_cast<const float4*>(&Q[g]);
        }
        __syncthreads();

        float zp[4][8] = {};
        float sq[4][8] = {};

        // inner reduction over d, 4-wide vector loads of z/s rows
        #pragma unroll 2
        for (int d = 0; d < D128; d += 4) {
            float za[4][4], sa[4][4];
            #pragma unroll
            for (int i = 0; i < 4; i++) {
                float4 tz = *reinterpret_cast<const float4*>(&zsh[(ty * 4 + i) * D128 + d]);
                float4 ts = *reinterpret_cast<const float4*>(&ssh[(ty * 4 + i) * D128 + d]);
                za[i][0] = tz.x; za[i][1] = tz.y; za[i][2] = tz.z; za[i][3] = tz.w;
                sa[i][0] = ts.x; sa[i][1] = ts.y; sa[i][2] = ts.z; sa[i][3] = ts.w;
            }
            #pragma unroll
            for (int dd = 0; dd < 4; dd++) {
                float4 p0 = *reinterpret_cast<const float4*>(&Psh[(d + dd) * 128 + tx * 8]);
                float4 p1 = *reinterpret_cast<const float4*>(&Psh[(d + dd) * 128 + tx * 8 + 4]);
                float4 q0 = *reinterpret_cast<const float4*>(&Qsh[(d + dd) * 128 + tx * 8]);
                float4 q1 = *reinterpret_cast<const float4*>(&Qsh[(d + dd) * 128 + tx * 8 + 4]);
                float pb[8] = {p0.x, p0.y, p0.z, p0.w, p1.x, p1.y, p1.z, p1.w};
                float qb[8] = {q0.x, q0.y, q0.z, q0.w, q1.x, q1.y, q1.z, q1.w};
                #pragma unroll
                for (int i = 0; i < 4; i++) {
                    float zv = za[i][dd];
                    float sv = sa[i][dd];
                    #pragma unroll
                    for (int j = 0; j < 8; j++) {
                        zp[i][j] += zv * pb[j];
                        sq[i][j] += sv * qb[j];
                    }
                }
            }
        }

        // epilogue: bili[m][k] = sum over 16 r = (this thread's 8 r) + (xor-1 lane's 8 r)
        #pragma unroll
        for (int i = 0; i < 4; i++) {
            float b = 0.f;
            #pragma unroll
            for (int j = 0; j < 8; j++) b += zp[i][j] * sq[i][j];
            b += __shfl_xor_sync(0xffffffffu, b, 1);
            if (!(tx & 1)) {
                int k = k0 + (tx >> 1);
                int mloc = ty * 4 + i;
                out[(size_t)(mbase + mloc) * KTOT + k] = linsh[mloc * KTOT + k] + b;
            }
        }
        __syncthreads();   // protect Psh/Qsh before next stage-in
    }
}

extern "C" void kernel_launch(void* const* d_in, const int* in_sizes, int n_in,
                              void* d_out, int out_size)
{
    const float* x1 = (const float*)d_in[0];
    const float* x2 = (const float*)d_in[1];
    const float* W  = (const float*)d_in[2];
    const float* P  = (const float*)d_in[3];
    const float* Q  = (const float*)d_in[4];
    float* out = (float*)d_out;

    const int M = in_sizes[0] / D128;     // 131072 tokens
    const int blocks = M / MTILE;         // 2048

    cudaFuncSetAttribute(antisym_kernel,
                         cudaFuncAttributeMaxDynamicSharedMemorySize,
                         SMEM_FLOATS * (int)sizeof(float));

    antisym_kernel<<<blocks, THREADS, SMEM_FLOATS * sizeof(float)>>>(x1, x2, W, P, Q, out);
}

// round 3
// speedup vs baseline: 4.7966x; 4.7966x over previous
#include <cuda_runtime.h>
#include <cstdint>

// AntisymmetricLayer via legacy tensor-core mma.sync (tf32), family-portable PTX.
//   z = x1-x2, s = x1+x2 (tf32 rna)
//   zP = z @ P^T, sQ = s @ Q^T  (P,Q pre-transposed to [(k,r)][d] scratch)
//   lin = z @ W^T folded in as an extra n8 MMA tile per k-step
//   out[m][k] = lin + sum_r zP[m][(k,r)] * sQ[m][(k,r)]
//
// CTA: 128 tokens, 8 warps (4 M x 2 N). 16 k-groups of 4 k (64 cols).
// Warp tile: 32 tokens x 32 cols (2 m16 tiles x 4 n8 tiles), fused zP+sQ accumulators.
// Smem rows padded to 132 floats -> conflict-free fragment loads.

#define D128 128
#define KTOT 64
#define MTILE 128
#define NGRP 16
#define THREADS 256
#define RP 132   // padded row length in floats

// smem float offsets
#define ZSH 0
#define SSH (ZSH + MTILE * RP)          // 16896
#define PSH (SSH + MTILE * RP)          // 33792
#define QSH (PSH + 64 * RP)             // 42240
#define WSH (QSH + 64 * RP)             // 50688
#define SMEM_FLOATS (WSH + 8 * RP)      // 51744 -> 206976 bytes

__device__ __align__(16) float g_Pt[KTOT * 16 * D128];
__device__ __align__(16) float g_Qt[KTOT * 16 * D128];

__device__ __forceinline__ float to_tf32(float x) {
    uint32_t u; asm("cvt.rna.tf32.f32 %0, %1;" : "=r"(u) : "f"(x));
    return __uint_as_float(u);
}

__device__ __forceinline__ void mma_tf32(float* d, const uint32_t* a, const uint32_t* b) {
    asm volatile("mma.sync.aligned.m16n8k8.row.col.f32.tf32.tf32.f32 "
                 "{%0,%1,%2,%3}, {%4,%5,%6,%7}, {%8,%9}, {%0,%1,%2,%3};"
                 : "+f"(d[0]), "+f"(d[1]), "+f"(d[2]), "+f"(d[3])
                 : "r"(a[0]), "r"(a[1]), "r"(a[2]), "r"(a[3]),
                   "r"(b[0]), "r"(b[1]));
}

// ---------------- pre-transpose P,Q -> [(k,r)][d], tf32-rounded ----------------
__global__ void transpose_pq(const float* __restrict__ P, const float* __restrict__ Q) {
    int i = blockIdx.x * 256 + threadIdx.x;      // i = (k*128+d)*16 + r, 131072 total
    int r = i & 15, d = (i >> 4) & 127, k = i >> 11;
    int o = (k * 16 + r) * 128 + d;
    g_Pt[o] = to_tf32(P[i]);
    g_Qt[o] = to_tf32(Q[i]);
}

// ---------------- main kernel ----------------
__global__ __launch_bounds__(THREADS, 1)
void antisym_mma(const float* __restrict__ x1, const float* __restrict__ x2,
                 const float* __restrict__ W, float* __restrict__ out)
{
    extern __shared__ float sh[];
    const int tid = threadIdx.x;
    const int lane = tid & 31;
    const int wid = tid >> 5;
    const int wm = wid & 3;        // M-warp 0..3
    const int wn = wid >> 2;       // N-warp 0..1
    const int g4 = lane >> 2;      // 0..7
    const int c4 = lane & 3;       // 0..3
    const int mbase = blockIdx.x * MTILE;

    // ---- stage z,s (tf32) ----
    {
        const float4* x1v = reinterpret_cast<const float4*>(x1) + (size_t)mbase * 32;
        const float4* x2v = reinterpret_cast<const float4*>(x2) + (size_t)mbase * 32;
        #pragma unroll
        for (int it = 0; it < 16; it++) {
            int idx = it * THREADS + tid;            // 4096 float4s
            int m = idx >> 5, d4 = idx & 31;
            float4 a = x1v[idx], b = x2v[idx];
            float4 z = make_float4(to_tf32(a.x - b.x), to_tf32(a.y - b.y),
                                   to_tf32(a.z - b.z), to_tf32(a.w - b.w));
            float4 s = make_float4(to_tf32(a.x + b.x), to_tf32(a.y + b.y),
                                   to_tf32(a.z + b.z), to_tf32(a.w + b.w));
            *reinterpret_cast<float4*>(&sh[ZSH + m * RP + d4 * 4]) = z;
            *reinterpret_cast<float4*>(&sh[SSH + m * RP + d4 * 4]) = s;
        }
        // zero W rows 4..7 (persist across groups)
        if (tid < 128) {
            int row = 4 + (tid >> 5), d4 = tid & 31;
            *reinterpret_cast<float4*>(&sh[WSH + row * RP + d4 * 4]) =
                make_float4(0.f, 0.f, 0.f, 0.f);
        }
    }

    // per-thread fragment base offsets (k-step adds ks*8)
    const int arow0 = wm * 32 + g4;                 // tile i adds i*16
    const uint32_t* zbase = reinterpret_cast<const uint32_t*>(sh + ZSH);
    const uint32_t* sbase = reinterpret_cast<const uint32_t*>(sh + SSH);
    const uint32_t* pbase = reinterpret_cast<const uint32_t*>(sh + PSH);
    const uint32_t* qbase = reinterpret_cast<const uint32_t*>(sh + QSH);
    const uint32_t* wbase = reinterpret_cast<const uint32_t*>(sh + WSH);
    const int nrow0 = wn * 32 + g4;                 // tile j adds j*8

    // ---- group loop: 4 k per group ----
    for (int g = 0; g < NGRP; g++) {
        __syncthreads();   // previous group's readers done before restage

        // stage P,Q slab (64 cols x 128 d) from pre-transposed scratch
        {
            const float4* Pv = reinterpret_cast<const float4*>(g_Pt) + g * 2048;
            const float4* Qv = reinterpret_cast<const float4*>(g_Qt) + g * 2048;
            #pragma unroll
            for (int it = 0; it < 8; it++) {
                int idx = it * THREADS + tid;        // 2048 float4s
                int n = idx >> 5, d4 = idx & 31;
                *reinterpret_cast<float4*>(&sh[PSH + n * RP + d4 * 4]) = Pv[idx];
                *reinterpret_cast<float4*>(&sh[QSH + n * RP + d4 * 4]) = Qv[idx];
            }
            // stage W rows 0..3 = W[g*4 .. g*4+3][:]
            if (tid < 128) {
                int row = tid >> 5, d4 = tid & 31;
                float4 w = reinterpret_cast<const float4*>(W)[(g * 4 + row) * 32 + d4];
                w = make_float4(to_tf32(w.x), to_tf32(w.y), to_tf32(w.z), to_tf32(w.w));
                *reinterpret_cast<float4*>(&sh[WSH + row * RP + d4 * 4]) = w;
            }
        }
        __syncthreads();

        float zp[2][4][4] = {};   // [i][j][reg]
        float sq[2][4][4] = {};
        float lw[2][4]    = {};   // lin acc [i][reg]

        #pragma unroll
        for (int ks = 0; ks < 16; ks++) {
            const int kb = ks * 8 + c4;
            uint32_t az[2][4], as_[2][4];
            #pragma unroll
            for (int i = 0; i < 2; i++) {
                int r0 = (arow0 + i * 16) * RP + kb;
                az[i][0] = zbase[r0];
                az[i][1] = zbase[r0 + 8 * RP];
                az[i][2] = zbase[r0 + 4];
                az[i][3] = zbase[r0 + 8 * RP + 4];
                as_[i][0] = sbase[r0];
                as_[i][1] = sbase[r0 + 8 * RP];
                as_[i][2] = sbase[r0 + 4];
                as_[i][3] = sbase[r0 + 8 * RP + 4];
            }
            uint32_t bp[4][2], bq[4][2], bw[2];
            #pragma unroll
            for (int j = 0; j < 4; j++) {
                int nb = (nrow0 + j * 8) * RP + kb;
                bp[j][0] = pbase[nb];
                bp[j][1] = pbase[nb + 4];
                bq[j][0] = qbase[nb];
                bq[j][1] = qbase[nb + 4];
            }
            bw[0] = wbase[g4 * RP + kb];
            bw[1] = wbase[g4 * RP + kb + 4];

            #pragma unroll
            for (int i = 0; i < 2; i++) {
                #pragma unroll
                for (int j = 0; j < 4; j++) {
                    mma_tf32(zp[i][j], az[i], bp[j]);
                    mma_tf32(sq[i][j], as_[i], bq[j]);
                }
                mma_tf32(lw[i], az[i], bw);
            }
        }

        // ---- epilogue: reduce r, add lin, store ----
        const int kA = g * 4 + wn * 2;
        #pragma unroll
        for (int i = 0; i < 2; i++) {
            // k_a from tiles j=0,1 ; k_b from tiles j=2,3
            float pa0 = zp[i][0][0]*sq[i][0][0] + zp[i][0][1]*sq[i][0][1]
                      + zp[i][1][0]*sq[i][1][0] + zp[i][1][1]*sq[i][1][1];
            float pa1 = zp[i][0][2]*sq[i][0][2] + zp[i][0][3]*sq[i][0][3]
                      + zp[i][1][2]*sq[i][1][2] + zp[i][1][3]*sq[i][1][3];
            float pb0 = zp[i][2][0]*sq[i][2][0] + zp[i][2][1]*sq[i][2][1]
                      + zp[i][3][0]*sq[i][3][0] + zp[i][3][1]*sq[i][3][1];
            float pb1 = zp[i][2][2]*sq[i][2][2] + zp[i][2][3]*sq[i][2][3]
                      + zp[i][3][2]*sq[i][3][2] + zp[i][3][3]*sq[i][3][3];
            pa0 += __shfl_xor_sync(~0u, pa0, 1); pa0 += __shfl_xor_sync(~0u, pa0, 2);
            pa1 += __shfl_xor_sync(~0u, pa1, 1); pa1 += __shfl_xor_sync(~0u, pa1, 2);
            pb0 += __shfl_xor_sync(~0u, pb0, 1); pb0 += __shfl_xor_sync(~0u, pb0, 2);
            pb1 += __shfl_xor_sync(~0u, pb1, 1); pb1 += __shfl_xor_sync(~0u, pb1, 2);
            if (c4 == wn) {
                // lin cols 2*wn, 2*wn+1 live in regs [0],[1] (row) / [2],[3] (row+8)
                int m0 = mbase + wm * 32 + i * 16 + g4;
                float2 o0 = make_float2(lw[i][0] + pa0, lw[i][1] + pb0);
                float2 o1 = make_float2(lw[i][2] + pa1, lw[i][3] + pb1);
                *reinterpret_cast<float2*>(&out[(size_t)m0 * KTOT + kA]) = o0;
                *reinterpret_cast<float2*>(&out[(size_t)(m0 + 8) * KTOT + kA]) = o1;
            }
        }
    }
}

extern "C" void kernel_launch(void* const* d_in, const int* in_sizes, int n_in,
                              void* d_out, int out_size)
{
    const float* x1 = (const float*)d_in[0];
    const float* x2 = (const float*)d_in[1];
    const float* W  = (const float*)d_in[2];
    const float* P  = (const float*)d_in[3];
    const float* Q  = (const float*)d_in[4];
    float* out = (float*)d_out;

    transpose_pq<<<512, 256>>>(P, Q);

    const int tokens = in_sizes[0] / D128;
    const int blocks = tokens / MTILE;      // 1024

    cudaFuncSetAttribute(antisym_mma,
                         cudaFuncAttributeMaxDynamicSharedMemorySize,
                         SMEM_FLOATS * (int)sizeof(float));
    antisym_mma<<<blocks, THREADS, SMEM_FLOATS * sizeof(float)>>>(x1, x2, W, out);
}

// round 4
// speedup vs baseline: 9.3978x; 1.9593x over previous
#include <cuda_runtime.h>
#include <cuda_fp16.h>
#include <cstdint>

// AntisymmetricLayer via fp16 mma.sync.m16n8k16 (fp32 accum), family-portable PTX.
//   z = x1-x2, s = x1+x2 (fp16 rn; fp16 mantissa == tf32 mantissa)
//   zP = z @ P^T, sQ = s @ Q^T  (P,Q pre-transposed to [(k,r)][d] fp16 scratch)
//   lin = z @ W^T folded in as an extra n8 MMA per k-step
//   out[m][k] = lin + sum_r zP[m][(k,r)] * sQ[m][(k,r)]
//
// CTA: 128 tokens, 8 warps (4M x 2N), 104KB smem -> 2 CTAs/SM (16 warps).
// Warp tile 32 tokens x 32 cols, ldmatrix fragment loads, RP=136 halfs (conflict-free).

#define D128 128
#define KTOT 64
#define MTILE 128
#define NGRP 16
#define THREADS 256
#define RP 136   // halfs per padded row (272B = 17*16B)

// smem half-offsets
#define ZSH 0
#define SSH (ZSH + MTILE * RP)        // 17408
#define PSH (SSH + MTILE * RP)        // 34816
#define QSH (PSH + 64 * RP)           // 43520
#define WSH (QSH + 64 * RP)           // 52224
#define SMEM_HALFS (WSH + 8 * RP)     // 53312 -> 106624 bytes

__device__ __align__(16) __half g_Pt[KTOT * 16 * D128];
__device__ __align__(16) __half g_Qt[KTOT * 16 * D128];

__device__ __forceinline__ uint32_t smem_u32(const void* p) {
    uint32_t a;
    asm("{ .reg .u64 t; cvta.to.shared.u64 t, %1; cvt.u32.u64 %0, t; }" : "=r"(a) : "l"(p));
    return a;
}

#define LDSM_X4(r0, r1, r2, r3, a) \
    asm volatile("ldmatrix.sync.aligned.m8n8.x4.shared.b16 {%0,%1,%2,%3}, [%4];" \
        : "=r"(r0), "=r"(r1), "=r"(r2), "=r"(r3) : "r"(a))
#define LDSM_X2(r0, r1, a) \
    asm volatile("ldmatrix.sync.aligned.m8n8.x2.shared.b16 {%0,%1}, [%2];" \
        : "=r"(r0), "=r"(r1) : "r"(a))

__device__ __forceinline__ void mma_f16(float* d, const uint32_t* a, const uint32_t* b) {
    asm volatile("mma.sync.aligned.m16n8k16.row.col.f32.f16.f16.f32 "
                 "{%0,%1,%2,%3}, {%4,%5,%6,%7}, {%8,%9}, {%0,%1,%2,%3};"
                 : "+f"(d[0]), "+f"(d[1]), "+f"(d[2]), "+f"(d[3])
                 : "r"(a[0]), "r"(a[1]), "r"(a[2]), "r"(a[3]),
                   "r"(b[0]), "r"(b[1]));
}

// ---------------- pre-transpose P,Q -> [(k,r)][d] fp16 ----------------
__global__ void transpose_pq(const float* __restrict__ P, const float* __restrict__ Q) {
    int i = blockIdx.x * 256 + threadIdx.x;   // i = (k*128+d)*16 + r
    int r = i & 15, d = (i >> 4) & 127, k = i >> 11;
    int o = (k * 16 + r) * 128 + d;
    g_Pt[o] = __float2half_rn(P[i]);
    g_Qt[o] = __float2half_rn(Q[i]);
}

// ---------------- main kernel ----------------
__global__ __launch_bounds__(THREADS, 2)
void antisym_h(const float* __restrict__ x1, const float* __restrict__ x2,
               const float* __restrict__ W, float* __restrict__ out)
{
    extern __shared__ __half shh[];
    const uint32_t smb = smem_u32(shh);
    const int tid = threadIdx.x;
    const int lane = tid & 31;
    const int wid = tid >> 5;
    const int wm = wid & 3;        // M-warp 0..3
    const int wn = wid >> 2;       // N-warp 0..1
    const int g4 = lane >> 2;
    const int c4 = lane & 3;
    const int mbase = blockIdx.x * MTILE;

    // ---- stage z,s as fp16 ----
    {
        const float4* x1v = reinterpret_cast<const float4*>(x1) + (size_t)mbase * 32;
        const float4* x2v = reinterpret_cast<const float4*>(x2) + (size_t)mbase * 32;
        #pragma unroll
        for (int it = 0; it < 8; it++) {
            int idx = it * THREADS + tid;            // 2048 chunks of 8 halfs
            int m = idx >> 4, d8 = idx & 15;
            float4 a0 = x1v[m * 32 + d8 * 2];
            float4 a1 = x1v[m * 32 + d8 * 2 + 1];
            float4 b0 = x2v[m * 32 + d8 * 2];
            float4 b1 = x2v[m * 32 + d8 * 2 + 1];
            half2 zz[4], ss[4];
            zz[0] = __floats2half2_rn(a0.x - b0.x, a0.y - b0.y);
            zz[1] = __floats2half2_rn(a0.z - b0.z, a0.w - b0.w);
            zz[2] = __floats2half2_rn(a1.x - b1.x, a1.y - b1.y);
            zz[3] = __floats2half2_rn(a1.z - b1.z, a1.w - b1.w);
            ss[0] = __floats2half2_rn(a0.x + b0.x, a0.y + b0.y);
            ss[1] = __floats2half2_rn(a0.z + b0.z, a0.w + b0.w);
            ss[2] = __floats2half2_rn(a1.x + b1.x, a1.y + b1.y);
            ss[3] = __floats2half2_rn(a1.z + b1.z, a1.w + b1.w);
            *reinterpret_cast<uint4*>(&shh[ZSH + m * RP + d8 * 8]) =
                *reinterpret_cast<uint4*>(zz);
            *reinterpret_cast<uint4*>(&shh[SSH + m * RP + d8 * 8]) =
                *reinterpret_cast<uint4*>(ss);
        }
        // zero W rows 4..7 (persist across groups)
        if (tid < 128) {
            int row = 4 + (tid >> 5), d4 = tid & 31;
            *reinterpret_cast<uint2*>(&shh[WSH + row * RP + d4 * 4]) = make_uint2(0u, 0u);
        }
    }

    // ---- per-lane ldmatrix byte addresses (add ks*32 per k-step) ----
    const int arow = (lane & 7) + ((lane >> 3) & 1) * 8;
    const uint32_t akoff = (uint32_t)(lane >> 4) * 16;
    uint32_t pAz[2], pAs[2];
    #pragma unroll
    for (int i = 0; i < 2; i++) {
        pAz[i] = smb + (uint32_t)(ZSH + (wm * 32 + i * 16 + arow) * RP) * 2 + akoff;
        pAs[i] = smb + (uint32_t)(SSH + (wm * 32 + i * 16 + arow) * RP) * 2 + akoff;
    }
    const int brow = lane & 7;
    const uint32_t bkoff = (uint32_t)((lane >> 3) & 1) * 16;
    uint32_t pP[4], pQ[4];
    #pragma unroll
    for (int j = 0; j < 4; j++) {
        pP[j] = smb + (uint32_t)(PSH + (wn * 32 + j * 8 + brow) * RP) * 2 + bkoff;
        pQ[j] = smb + (uint32_t)(QSH + (wn * 32 + j * 8 + brow) * RP) * 2 + bkoff;
    }
    const uint32_t pW = smb + (uint32_t)(WSH + brow * RP) * 2 + bkoff;

    // ---- group loop: 4 k per group ----
    for (int g = 0; g < NGRP; g++) {
        __syncthreads();    // previous group's readers done

        // stage P,Q slab (64 cols x 128 d, fp16)
        {
            const uint4* Pv = reinterpret_cast<const uint4*>(g_Pt) + g * 1024;
            const uint4* Qv = reinterpret_cast<const uint4*>(g_Qt) + g * 1024;
            #pragma unroll
            for (int it = 0; it < 4; it++) {
                int idx = it * THREADS + tid;        // 1024 chunks of 8 halfs
                int n = idx >> 4, d8 = idx & 15;
                *reinterpret_cast<uint4*>(&shh[PSH + n * RP + d8 * 8]) = Pv[idx];
                *reinterpret_cast<uint4*>(&shh[QSH + n * RP + d8 * 8]) = Qv[idx];
            }
            if (tid < 128) {
                int row = tid >> 5, d4 = tid & 31;
                float4 w = reinterpret_cast<const float4*>(W)[(g * 4 + row) * 32 + d4];
                half2 w01 = __floats2half2_rn(w.x, w.y);
                half2 w23 = __floats2half2_rn(w.z, w.w);
                uint2 wp = make_uint2(*reinterpret_cast<uint32_t*>(&w01),
                                      *reinterpret_cast<uint32_t*>(&w23));
                *reinterpret_cast<uint2*>(&shh[WSH + row * RP + d4 * 4]) = wp;
            }
        }
        __syncthreads();

        float zp[2][4][4] = {};
        float sq[2][4][4] = {};
        float lw[2][4]    = {};

        #pragma unroll
        for (int ks = 0; ks < 8; ks++) {
            const uint32_t ko = (uint32_t)ks * 32;
            uint32_t az[2][4], as_[2][4];
            #pragma unroll
            for (int i = 0; i < 2; i++) {
                LDSM_X4(az[i][0], az[i][1], az[i][2], az[i][3], pAz[i] + ko);
                LDSM_X4(as_[i][0], as_[i][1], as_[i][2], as_[i][3], pAs[i] + ko);
            }
            uint32_t bw[2];
            LDSM_X2(bw[0], bw[1], pW + ko);
            uint32_t bp[4][2], bq[4][2];
            #pragma unroll
            for (int j = 0; j < 4; j++) {
                LDSM_X2(bp[j][0], bp[j][1], pP[j] + ko);
                LDSM_X2(bq[j][0], bq[j][1], pQ[j] + ko);
            }
            #pragma unroll
            for (int i = 0; i < 2; i++) {
                #pragma unroll
                for (int j = 0; j < 4; j++) {
                    mma_f16(zp[i][j], az[i], bp[j]);
                    mma_f16(sq[i][j], as_[i], bq[j]);
                }
                mma_f16(lw[i], az[i], bw);
            }
        }

        // ---- epilogue: reduce r, add lin, store ----
        const int kA = g * 4 + wn * 2;
        #pragma unroll
        for (int i = 0; i < 2; i++) {
            float pa0 = zp[i][0][0]*sq[i][0][0] + zp[i][0][1]*sq[i][0][1]
                      + zp[i][1][0]*sq[i][1][0] + zp[i][1][1]*sq[i][1][1];
            float pa1 = zp[i][0][2]*sq[i][0][2] + zp[i][0][3]*sq[i][0][3]
                      + zp[i][1][2]*sq[i][1][2] + zp[i][1][3]*sq[i][1][3];
            float pb0 = zp[i][2][0]*sq[i][2][0] + zp[i][2][1]*sq[i][2][1]
                      + zp[i][3][0]*sq[i][3][0] + zp[i][3][1]*sq[i][3][1];
            float pb1 = zp[i][2][2]*sq[i][2][2] + zp[i][2][3]*sq[i][2][3]
                      + zp[i][3][2]*sq[i][3][2] + zp[i][3][3]*sq[i][3][3];
            pa0 += __shfl_xor_sync(~0u, pa0, 1); pa0 += __shfl_xor_sync(~0u, pa0, 2);
            pa1 += __shfl_xor_sync(~0u, pa1, 1); pa1 += __shfl_xor_sync(~0u, pa1, 2);
            pb0 += __shfl_xor_sync(~0u, pb0, 1); pb0 += __shfl_xor_sync(~0u, pb0, 2);
            pb1 += __shfl_xor_sync(~0u, pb1, 1); pb1 += __shfl_xor_sync(~0u, pb1, 2);
            if (c4 == wn) {
                int m0 = mbase + wm * 32 + i * 16 + g4;
                float2 o0 = make_float2(lw[i][0] + pa0, lw[i][1] + pb0);
                float2 o1 = make_float2(lw[i][2] + pa1, lw[i][3] + pb1);
                *reinterpret_cast<float2*>(&out[(size_t)m0 * KTOT + kA]) = o0;
                *reinterpret_cast<float2*>(&out[(size_t)(m0 + 8) * KTOT + kA]) = o1;
            }
        }
    }
}

extern "C" void kernel_launch(void* const* d_in, const int* in_sizes, int n_in,
                              void* d_out, int out_size)
{
    const float* x1 = (const float*)d_in[0];
    const float* x2 = (const float*)d_in[1];
    const float* W  = (const float*)d_in[2];
    const float* P  = (const float*)d_in[3];
    const float* Q  = (const float*)d_in[4];
    float* out = (float*)d_out;

    transpose_pq<<<512, 256>>>(P, Q);

    const int tokens = in_sizes[0] / D128;
    const int blocks = tokens / MTILE;      // 1024

    cudaFuncSetAttribute(antisym_h,
                         cudaFuncAttributeMaxDynamicSharedMemorySize,
                         SMEM_HALFS * (int)sizeof(__half));
    antisym_h<<<blocks, THREADS, SMEM_HALFS * sizeof(__half)>>>(x1, x2, W, out);
}

// round 5
// speedup vs baseline: 10.1018x; 1.0749x over previous
#include <cuda_runtime.h>
#include <cuda_fp16.h>
#include <cstdint>

// AntisymmetricLayer via fp16 mma.sync.m16n8k16 (fp32 accum).
//   z = x1-x2, s = x1+x2 (fp16 rn)
//   Phase L: lin = z @ W^T -> stored to out (dense n8 tiles, no waste)
//   Main: zP = z @ P^T, sQ = s @ Q^T per 4-k group; epilogue RMW: out += sum_r zP*sQ
// CTA: 128 tokens, 8 warps (4M x 2N), 96KB smem (XOR-swizzled 256B rows) -> 2 CTAs/SM.
// P,Q staged via cp.async in two d-halves, software-pipelined across groups.

#define D128 128
#define KTOT 64
#define MTILE 128
#define NGRP 16
#define THREADS 256

// smem byte offsets (rows of 256B = 128 halfs, XOR-swizzled 16B chunks)
#define ZSH 0
#define SSH 32768
#define PSH 65536
#define QSH 81920
#define SMEM_BYTES 98304   // 96KB

__device__ __align__(16) __half g_Pt[KTOT * 16 * D128];
__device__ __align__(16) __half g_Qt[KTOT * 16 * D128];

__device__ __forceinline__ uint32_t smem_u32(const void* p) {
    uint32_t a;
    asm("{ .reg .u64 t; cvta.to.shared.u64 t, %1; cvt.u32.u64 %0, t; }" : "=r"(a) : "l"(p));
    return a;
}

#define LDSM_X4(r0, r1, r2, r3, a) \
    asm volatile("ldmatrix.sync.aligned.m8n8.x4.shared.b16 {%0,%1,%2,%3}, [%4];" \
        : "=r"(r0), "=r"(r1), "=r"(r2), "=r"(r3) : "r"(a))

#define CP_ASYNC16(dst, src) \
    asm volatile("cp.async.cg.shared.global [%0], [%1], 16;" :: "r"(dst), "l"(src))
#define CP_COMMIT() asm volatile("cp.async.commit_group;" ::: "memory")
#define CP_WAIT(N)  asm volatile("cp.async.wait_group %0;" :: "n"(N) : "memory")

__device__ __forceinline__ void mma_f16(float* d, const uint32_t* a, const uint32_t* b) {
    asm volatile("mma.sync.aligned.m16n8k16.row.col.f32.f16.f16.f32 "
                 "{%0,%1,%2,%3}, {%4,%5,%6,%7}, {%8,%9}, {%0,%1,%2,%3};"
                 : "+f"(d[0]), "+f"(d[1]), "+f"(d[2]), "+f"(d[3])
                 : "r"(a[0]), "r"(a[1]), "r"(a[2]), "r"(a[3]),
                   "r"(b[0]), "r"(b[1]));
}

// ---------------- pre-transpose P,Q -> [(k,r)][d] fp16 ----------------
__global__ void transpose_pq(const float* __restrict__ P, const float* __restrict__ Q) {
    int i = blockIdx.x * 256 + threadIdx.x;   // i = (k*128+d)*16 + r
    int r = i & 15, d = (i >> 4) & 127, k = i >> 11;
    int o = (k * 16 + r) * 128 + d;
    g_Pt[o] = __float2half_rn(P[i]);
    g_Qt[o] = __float2half_rn(Q[i]);
}

// issue cp.async for half h (d-chunks h*8..h*8+7) of group g's P,Q slabs
__device__ __forceinline__ void stage_pq(uint32_t smb, int g, int h, int tid) {
    const char* gp = reinterpret_cast<const char*>(g_Pt);
    const char* gq = reinterpret_cast<const char*>(g_Qt);
    #pragma unroll
    for (int cc = 0; cc < 2; cc++) {
        int lin = tid * 2 + cc;          // 0..511
        int n = lin >> 3;                // col 0..63
        int c = (lin & 7) + h * 8;       // chunk 0..15
        uint32_t so = (uint32_t)(n * 256 + (((c) ^ (n & 7)) << 4));
        int64_t go = ((int64_t)(g * 64 + n) * 128 + c * 8) * 2;
        CP_ASYNC16(smb + PSH + so, gp + go);
        CP_ASYNC16(smb + QSH + so, gq + go);
    }
}

// ---------------- main kernel ----------------
__global__ __launch_bounds__(THREADS, 2)
void antisym_h(const float* __restrict__ x1, const float* __restrict__ x2,
               const float* __restrict__ W, float* __restrict__ out)
{
    extern __shared__ char shm[];
    const uint32_t smb = smem_u32(shm);
    const int tid = threadIdx.x;
    const int lane = tid & 31;
    const int wid = tid >> 5;
    const int wm = wid & 3;
    const int wn = wid >> 2;
    const int g4 = lane >> 2;
    const int c4 = lane & 3;
    const int mbase = blockIdx.x * MTILE;

    // ---- stage z,s as fp16 (swizzled) + W into PSH region ----
    {
        const float4* x1v = reinterpret_cast<const float4*>(x1) + (size_t)mbase * 32;
        const float4* x2v = reinterpret_cast<const float4*>(x2) + (size_t)mbase * 32;
        #pragma unroll
        for (int it = 0; it < 8; it++) {
            int idx = it * THREADS + tid;            // 2048 chunks
            int m = idx >> 4, c = idx & 15;
            float4 a0 = x1v[m * 32 + c * 2];
            float4 a1 = x1v[m * 32 + c * 2 + 1];
            float4 b0 = x2v[m * 32 + c * 2];
            float4 b1 = x2v[m * 32 + c * 2 + 1];
            half2 zz[4], ss[4];
            zz[0] = __floats2half2_rn(a0.x - b0.x, a0.y - b0.y);
            zz[1] = __floats2half2_rn(a0.z - b0.z, a0.w - b0.w);
            zz[2] = __floats2half2_rn(a1.x - b1.x, a1.y - b1.y);
            zz[3] = __floats2half2_rn(a1.z - b1.z, a1.w - b1.w);
            ss[0] = __floats2half2_rn(a0.x + b0.x, a0.y + b0.y);
            ss[1] = __floats2half2_rn(a0.z + b0.z, a0.w + b0.w);
            ss[2] = __floats2half2_rn(a1.x + b1.x, a1.y + b1.y);
            ss[3] = __floats2half2_rn(a1.z + b1.z, a1.w + b1.w);
            uint32_t so = (uint32_t)(m * 256 + ((c ^ (m & 7)) << 4));
            *reinterpret_cast<uint4*>(shm + ZSH + so) = *reinterpret_cast<uint4*>(zz);
            *reinterpret_cast<uint4*>(shm + SSH + so) = *reinterpret_cast<uint4*>(ss);
        }
        // W (64 rows x 128 halfs) into PSH region, swizzled
        #pragma unroll
        for (int it = 0; it < 4; it++) {
            int idx = it * THREADS + tid;            // 1024 chunks
            int r = idx >> 4, c = idx & 15;
            float4 w0 = reinterpret_cast<const float4*>(W)[r * 32 + c * 2];
            float4 w1 = reinterpret_cast<const float4*>(W)[r * 32 + c * 2 + 1];
            half2 ww[4];
            ww[0] = __floats2half2_rn(w0.x, w0.y);
            ww[1] = __floats2half2_rn(w0.z, w0.w);
            ww[2] = __floats2half2_rn(w1.x, w1.y);
            ww[3] = __floats2half2_rn(w1.z, w1.w);
            uint32_t so = (uint32_t)(r * 256 + ((c ^ (r & 7)) << 4));
            *reinterpret_cast<uint4*>(shm + PSH + so) = *reinterpret_cast<uint4*>(ww);
        }
    }
    __syncthreads();

    // ---- per-lane fragment row bases ----
    const int xr = lane & 7;
    // A: rows for z/s ldmatrix.x4 (lanes 0-15 rows, 16-31 same rows k-chunk+1)
    uint32_t rowA[2];
    #pragma unroll
    for (int i = 0; i < 2; i++)
        rowA[i] = (uint32_t)((wm * 32 + i * 16 + ((lane >> 3) & 1) * 8 + xr) * 256);
    const int krelA = lane >> 4;          // A k-chunk select
    const int krelB = (lane >> 3) & 1;    // B k-chunk select
    const uint32_t bArr = (lane < 16) ? (smb + PSH) : (smb + QSH);  // P | Q per half-warp
    uint32_t rowB[4];
    #pragma unroll
    for (int j = 0; j < 4; j++)
        rowB[j] = bArr + (uint32_t)((wn * 32 + j * 8 + xr) * 256);

    // ---- Phase L: lin = z @ W^T (dense), store to out ----
    {
        // B: W tiles; one x4 covers tiles (t, t+1): lanes<16 tile t, >=16 tile t+1
        uint32_t rowW[2];
        #pragma unroll
        for (int j2 = 0; j2 < 2; j2++)
            rowW[j2] = smb + PSH +
                (uint32_t)(((wn * 4 + j2 * 2 + (lane >> 4)) * 8 + xr) * 256);

        float lw[2][4][4] = {};
        #pragma unroll
        for (int ks = 0; ks < 8; ks++) {
            uint32_t offA = (uint32_t)(((2 * ks + krelA) ^ xr) << 4);
            uint32_t offB = (uint32_t)(((2 * ks + krelB) ^ xr) << 4);
            uint32_t az[2][4];
            #pragma unroll
            for (int i = 0; i < 2; i++)
                LDSM_X4(az[i][0], az[i][1], az[i][2], az[i][3],
                        smb + ZSH + rowA[i] + offA);
            #pragma unroll
            for (int j2 = 0; j2 < 2; j2++) {
                uint32_t r0, r1, r2, r3;
                LDSM_X4(r0, r1, r2, r3, rowW[j2] + offB);
                uint32_t ba[2] = {r0, r1}, bb[2] = {r2, r3};
                #pragma unroll
                for (int i = 0; i < 2; i++) {
                    mma_f16(lw[i][j2 * 2],     az[i], ba);
                    mma_f16(lw[i][j2 * 2 + 1], az[i], bb);
                }
            }
        }
        #pragma unroll
        for (int i = 0; i < 2; i++) {
            int m0 = mbase + wm * 32 + i * 16 + g4;
            #pragma unroll
            for (int t = 0; t < 4; t++) {
                int k0 = wn * 32 + t * 8 + 2 * c4;
                *reinterpret_cast<float2*>(&out[(size_t)m0 * KTOT + k0]) =
                    make_float2(lw[i][t][0], lw[i][t][1]);
                *reinterpret_cast<float2*>(&out[(size_t)(m0 + 8) * KTOT + k0]) =
                    make_float2(lw[i][t][2], lw[i][t][3]);
            }
        }
    }
    __threadfence_block();
    __syncthreads();

    // ---- pipeline warmup: group 0 halves ----
    stage_pq(smb, 0, 0, tid); CP_COMMIT();
    stage_pq(smb, 0, 1, tid); CP_COMMIT();

    // ---- group loop: 4 k per group ----
    for (int g = 0; g < NGRP; g++) {
        CP_WAIT(1);
        __syncthreads();                  // half0(g) visible to all

        const int kA = g * 4 + wn * 2;
        const int mr0 = mbase + wm * 32 + g4;

        // prefetch lin from out (RMW)
        float2 l0[2], l1[2];
        if (c4 == wn) {
            #pragma unroll
            for (int i = 0; i < 2; i++) {
                l0[i] = *reinterpret_cast<const float2*>(&out[(size_t)(mr0 + i * 16) * KTOT + kA]);
                l1[i] = *reinterpret_cast<const float2*>(&out[(size_t)(mr0 + i * 16 + 8) * KTOT + kA]);
            }
        }

        float zp[2][4][4] = {};
        float sq[2][4][4] = {};

        #pragma unroll
        for (int ks = 0; ks < 4; ks++) {
            uint32_t offA = (uint32_t)(((2 * ks + krelA) ^ xr) << 4);
            uint32_t offB = (uint32_t)(((2 * ks + krelB) ^ xr) << 4);
            uint32_t az[2][4], as_[2][4];
            #pragma unroll
            for (int i = 0; i < 2; i++) {
                LDSM_X4(az[i][0], az[i][1], az[i][2], az[i][3], smb + ZSH + rowA[i] + offA);
                LDSM_X4(as_[i][0], as_[i][1], as_[i][2], as_[i][3], smb + SSH + rowA[i] + offA);
            }
            #pragma unroll
            for (int j = 0; j < 4; j++) {
                uint32_t r0, r1, r2, r3;
                LDSM_X4(r0, r1, r2, r3, rowB[j] + offB);
                uint32_t bp[2] = {r0, r1}, bq[2] = {r2, r3};
                #pragma unroll
                for (int i = 0; i < 2; i++) {
                    mma_f16(zp[i][j], az[i], bp);
                    mma_f16(sq[i][j], as_[i], bq);
                }
            }
        }
        __syncthreads();                  // half0 consumed
        if (g < NGRP - 1) { stage_pq(smb, g + 1, 0, tid); CP_COMMIT(); }
        if (g < NGRP - 1) { CP_WAIT(1); } else { CP_WAIT(0); }
        __syncthreads();                  // half1(g) visible

        #pragma unroll
        for (int ks = 4; ks < 8; ks++) {
            uint32_t offA = (uint32_t)(((2 * ks + krelA) ^ xr) << 4);
            uint32_t offB = (uint32_t)(((2 * ks + krelB) ^ xr) << 4);
            uint32_t az[2][4], as_[2][4];
            #pragma unroll
            for (int i = 0; i < 2; i++) {
                LDSM_X4(az[i][0], az[i][1], az[i][2], az[i][3], smb + ZSH + rowA[i] + offA);
                LDSM_X4(as_[i][0], as_[i][1], as_[i][2], as_[i][3], smb + SSH + rowA[i] + offA);
            }
            #pragma unroll
            for (int j = 0; j < 4; j++) {
                uint32_t r0, r1, r2, r3;
                LDSM_X4(r0, r1, r2, r3, rowB[j] + offB);
                uint32_t bp[2] = {r0, r1}, bq[2] = {r2, r3};
                #pragma unroll
                for (int i = 0; i < 2; i++) {
                    mma_f16(zp[i][j], az[i], bp);
                    mma_f16(sq[i][j], as_[i], bq);
                }
            }
        }

        // ---- epilogue: reduce r, RMW out ----
        #pragma unroll
        for (int i = 0; i < 2; i++) {
            float pa0 = zp[i][0][0]*sq[i][0][0] + zp[i][0][1]*sq[i][0][1]
                      + zp[i][1][0]*sq[i][1][0] + zp[i][1][1]*sq[i][1][1];
            float pa1 = zp[i][0][2]*sq[i][0][2] + zp[i][0][3]*sq[i][0][3]
                      + zp[i][1][2]*sq[i][1][2] + zp[i][1][3]*sq[i][1][3];
            float pb0 = zp[i][2][0]*sq[i][2][0] + zp[i][2][1]*sq[i][2][1]
                      + zp[i][3][0]*sq[i][3][0] + zp[i][3][1]*sq[i][3][1];
            float pb1 = zp[i][2][2]*sq[i][2][2] + zp[i][2][3]*sq[i][2][3]
                      + zp[i][3][2]*sq[i][3][2] + zp[i][3][3]*sq[i][3][3];
            pa0 += __shfl_xor_sync(~0u, pa0, 1); pa0 += __shfl_xor_sync(~0u, pa0, 2);
            pa1 += __shfl_xor_sync(~0u, pa1, 1); pa1 += __shfl_xor_sync(~0u, pa1, 2);
            pb0 += __shfl_xor_sync(~0u, pb0, 1); pb0 += __shfl_xor_sync(~0u, pb0, 2);
            pb1 += __shfl_xor_sync(~0u, pb1, 1); pb1 += __shfl_xor_sync(~0u, pb1, 2);
            if (c4 == wn) {
                int m0 = mr0 + i * 16;
                *reinterpret_cast<float2*>(&out[(size_t)m0 * KTOT + kA]) =
                    make_float2(l0[i].x + pa0, l0[i].y + pb0);
                *reinterpret_cast<float2*>(&out[(size_t)(m0 + 8) * KTOT + kA]) =
                    make_float2(l1[i].x + pa1, l1[i].y + pb1);
            }
        }

        __syncthreads();                  // half1 consumed
        if (g < NGRP - 1) { stage_pq(smb, g + 1, 1, tid); CP_COMMIT(); }
    }
}

extern "C" void kernel_launch(void* const* d_in, const int* in_sizes, int n_in,
                              void* d_out, int out_size)
{
    const float* x1 = (const float*)d_in[0];
    const float* x2 = (const float*)d_in[1];
    const float* W  = (const float*)d_in[2];
    const float* P  = (const float*)d_in[3];
    const float* Q  = (const float*)d_in[4];
    float* out = (float*)d_out;

    transpose_pq<<<512, 256>>>(P, Q);

    const int tokens = in_sizes[0] / D128;
    const int blocks = tokens / MTILE;      // 1024

    cudaFuncSetAttribute(antisym_h,
                         cudaFuncAttributeMaxDynamicSharedMemorySize, SMEM_BYTES);
    antisym_h<<<blocks, THREADS, SMEM_BYTES>>>(x1, x2, W, out);
}